// round 15
// baseline (speedup 1.0000x reference)
#include <cuda_runtime.h>
#include <cuda_fp16.h>
#include <cstdint>

// ---------------------------------------------------------------------------
// CliffordLinear via Cl(3,0) ~= M2(C) + GAUSS 3-multiplication complex GEMM.
//   Y[b,o] = .5 * Wm[o,:] . Xm[:,b]  (2x2 complex),  blades rebuilt at the end.
// Complex GEMM: rows (b,c) [16384], cols (o,r) [512], k (i,cc) [512].
//   M1 = Ar.Br^T, M2 = Ai.Bi^T, M3 = (Ar+Ai).(Br+Bi)^T
//   Re Y = M1 - M2,  Im Y = M3 - M1 - M2
// -> 12.9 G-MAC (75% of the packed 4-mult form). fp16 operands, fp32 accum.
// ---------------------------------------------------------------------------

#define B_DIM 8192
#define CIN  256
#define COUT 256
#define M_A  16384          /* A real rows (b,c) */
#define K_R  512            /* real k per product */
#define N_C  512            /* complex cols (o,r) */

// 3 contiguous streams each: A: [3][16384 x 512], B: [3][512 x 512]
__device__ __half g_A[3 * M_A * K_R];     // 48 MB  (Ar | Ai | As)
__device__ __half g_B[3 * N_C * K_R];     // 1.5 MB (Br | Bi | Bs)

// ---------------------------------------------------------------------------
// Prologue 1: x -> Ar, Ai, As.  One thread per (b,i).
//  row 2b   (c=0): cc0,cc1 = (m00, m10)
//  row 2b+1 (c=1): cc0,cc1 = (m01, m11)
//  m00=(x0+x4)+i(x3+x7)  m01=(x1-x5)+i(x6-x2)
//  m10=(x1+x5)+i(x2+x6)  m11=(x0-x4)+i(x7-x3)
// ---------------------------------------------------------------------------
__global__ void __launch_bounds__(1024) a_transform_kernel(const float4* __restrict__ x4) {
    int t = blockIdx.x * 1024 + threadIdx.x;       // (b,i)
    float4 v0 = x4[2 * t];                          // x0..x3
    float4 v1 = x4[2 * t + 1];                      // x4..x7
    int b = t >> 8, i = t & 255;
    __half2* Ar = reinterpret_cast<__half2*>(g_A);
    __half2* Ai = Ar + (M_A * K_R / 2);
    __half2* As = Ai + (M_A * K_R / 2);
    int r0 = (2 * b) * 256 + i;                    // half2 index, row 2b col 2i
    int r1 = r0 + 256;                             // row 2b+1
    float re0a = v0.x + v1.x, re0b = v0.y + v1.y;  // Re m00, Re m10
    float im0a = v0.w + v1.w, im0b = v0.z + v1.z;  // Im m00, Im m10
    float re1a = v0.y - v1.y, re1b = v0.x - v1.x;  // Re m01, Re m11
    float im1a = v1.z - v0.z, im1b = v1.w - v0.w;  // Im m01, Im m11
    Ar[r0] = __floats2half2_rn(re0a, re0b);
    Ai[r0] = __floats2half2_rn(im0a, im0b);
    As[r0] = __floats2half2_rn(re0a + im0a, re0b + im0b);
    Ar[r1] = __floats2half2_rn(re1a, re1b);
    Ai[r1] = __floats2half2_rn(im1a, im1b);
    As[r1] = __floats2half2_rn(re1a + im1a, re1b + im1b);
}

// ---------------------------------------------------------------------------
// Prologue 2: weight -> Br, Bi, Bs (x 0.5).  One thread per (o,i).
//  B row 2o+r, col 2i+cc = .5 * Wm[o,i](r,cc)
// ---------------------------------------------------------------------------
__global__ void __launch_bounds__(1024) b_transform_kernel(const float* __restrict__ w) {
    int t = blockIdx.x * 1024 + threadIdx.x;       // (o,i)
    int o = t >> 8, i = t & 255;
    const float* p = w + (size_t)t * 8;
    float w0 = p[0], w1 = p[1], w2 = p[2], w3 = p[3];
    float w4 = p[4], w5 = p[5], w6 = p[6], w7 = p[7];
    float Rm00 = .5f * (w0 + w4), Rm01 = .5f * (w1 - w5);
    float Rm10 = .5f * (w1 + w5), Rm11 = .5f * (w0 - w4);
    float Im00 = .5f * (w3 + w7), Im01 = .5f * (w6 - w2);
    float Im10 = .5f * (w2 + w6), Im11 = .5f * (w7 - w3);
    __half2* Br = reinterpret_cast<__half2*>(g_B);
    __half2* Bi = Br + (N_C * K_R / 2);
    __half2* Bs = Bi + (N_C * K_R / 2);
    int r0 = (2 * o) * 256 + i;                    // row 2o (r=0)
    int r1 = r0 + 256;                             // row 2o+1 (r=1)
    Br[r0] = __floats2half2_rn(Rm00, Rm01);
    Bi[r0] = __floats2half2_rn(Im00, Im01);
    Bs[r0] = __floats2half2_rn(Rm00 + Im00, Rm01 + Im01);
    Br[r1] = __floats2half2_rn(Rm10, Rm11);
    Bi[r1] = __floats2half2_rn(Im10, Im11);
    Bs[r1] = __floats2half2_rn(Rm10 + Im10, Rm11 + Im11);
}

// ---------------------------------------------------------------------------
// GEMM: CTA = 384 threads (12 warps).  Complex tile: 128 A-rows x 64 n_c.
// Products M1,M2,M3 each 128x64 real; warp w: product w>>2, 64x32 sub-tile.
// k-stage 64, 2-stage cp.async pipeline, 8 iterations.
// smem stage: [Ar|Ai|As](3 x 128 x 72h) + [Br|Bi|Bs](3 x 64 x 72h) = 82944 B.
// ---------------------------------------------------------------------------
#define BKP_H 72
#define ROW_B 144
#define A_ST_B (128 * ROW_B)               /* 18432 per A stream */
#define B_ST_B (64 * ROW_B)                /* 9216 per B stream */
#define A_REG_B (3 * A_ST_B)               /* 55296 */
#define STAGE_B (A_REG_B + 3 * B_ST_B)     /* 82944 */
#define SMEM_TOTAL (2 * STAGE_B)           /* 165888 */
#define NITER 8                            /* 512 / 64 */

__device__ __forceinline__ void mma_f16(float& c0, float& c1, float& c2, float& c3,
                                        uint32_t a0, uint32_t a1, uint32_t a2, uint32_t a3,
                                        uint32_t b0, uint32_t b1) {
    asm volatile(
        "mma.sync.aligned.m16n8k16.row.col.f32.f16.f16.f32 "
        "{%0,%1,%2,%3}, {%4,%5,%6,%7}, {%8,%9}, {%0,%1,%2,%3};"
        : "+f"(c0), "+f"(c1), "+f"(c2), "+f"(c3)
        : "r"(a0), "r"(a1), "r"(a2), "r"(a3), "r"(b0), "r"(b1));
}

#define COMPUTE_STAGE(aP, bP)                                                         \
    _Pragma("unroll")                                                                 \
    for (int q = 0; q < 2; q++) {                                                     \
        uint4 fb[4];                                                                  \
        _Pragma("unroll")                                                             \
        for (int ni = 0; ni < 4; ni++)                                                \
            fb[ni] = *reinterpret_cast<const uint4*>((bP) + ni * 8 * BKP_H + 8 * q);  \
        _Pragma("unroll")                                                             \
        for (int mi = 0; mi < 4; mi++) {                                              \
            uint4 fa0 = *reinterpret_cast<const uint4*>((aP) + (mi * 16    ) * BKP_H + 8 * q); \
            uint4 fa1 = *reinterpret_cast<const uint4*>((aP) + (mi * 16 + 8) * BKP_H + 8 * q); \
            const uint32_t* pa0 = &fa0.x;                                             \
            const uint32_t* pa1 = &fa1.x;                                             \
            _Pragma("unroll")                                                         \
            for (int kk = 0; kk < 2; kk++) {                                          \
                uint32_t a0 = pa0[2 * kk], a2 = pa0[2 * kk + 1];                      \
                uint32_t a1 = pa1[2 * kk], a3 = pa1[2 * kk + 1];                      \
                _Pragma("unroll")                                                     \
                for (int ni = 0; ni < 4; ni++) {                                      \
                    const uint32_t* pb = &fb[ni].x;                                   \
                    mma_f16(acc[mi][ni][0], acc[mi][ni][1],                           \
                            acc[mi][ni][2], acc[mi][ni][3],                           \
                            a0, a1, a2, a3, pb[2 * kk], pb[2 * kk + 1]);              \
                }                                                                     \
            }                                                                         \
        }                                                                             \
    }

#define EPROW 66                            /* epilogue product row stride, floats */
#define EPPROD (128 * EPROW)                /* 8448 floats per product */

__global__ void __launch_bounds__(384, 1) gemm_gauss_kernel(
    const float* __restrict__ bias, float* __restrict__ C)
{
    extern __shared__ __half smem[];
    const int tid  = threadIdx.x;
    const int wid  = tid >> 5;
    const int lane = tid & 31;
    const int p  = wid >> 2;                // product 0..2
    const int wm = (wid >> 1) & 1;          // M sub-tile
    const int wn = wid & 1;                 // N sub-tile
    const int lr = lane >> 2, lc = lane & 3;
    const int block_m = blockIdx.y * 128;   // A-row base
    const int nb = blockIdx.x;              // n_c tile (64 each)

    uint32_t smem_u;
    asm("{ .reg .u64 t; cvta.to.shared.u64 t, %1; cvt.u32.u64 %0, t; }"
        : "=r"(smem_u) : "l"(smem));

    // Loader: A 3072 16B-chunks (8/thread), B 1536 (4/thread)
#define LOADG(buf, k0) do {                                                           \
        uint32_t sb_ = smem_u + (uint32_t)(buf) * STAGE_B;                            \
        _Pragma("unroll")                                                             \
        for (int j_ = 0; j_ < 8; j_++) {                                              \
            int idx_ = j_ * 384 + tid;                                                \
            int row_ = idx_ >> 3, q_ = idx_ & 7;                                      \
            int str_ = row_ >> 7, lrow_ = row_ & 127;                                 \
            const __half* gm_ = g_A + (size_t)str_ * (M_A * K_R)                      \
                              + (size_t)(block_m + lrow_) * K_R + (k0) + q_ * 8;      \
            asm volatile("cp.async.cg.shared.global [%0], [%1], 16;"                  \
                :: "r"(sb_ + (uint32_t)(str_ * A_ST_B + lrow_ * ROW_B + q_ * 16)),    \
                   "l"(gm_));                                                         \
        }                                                                             \
        _Pragma("unroll")                                                             \
        for (int j_ = 0; j_ < 4; j_++) {                                              \
            int idx_ = j_ * 384 + tid;                                                \
            int row_ = idx_ >> 3, q_ = idx_ & 7;                                      \
            int str_ = row_ >> 6, lrow_ = row_ & 63;                                  \
            const __half* gm_ = g_B + (size_t)str_ * (N_C * K_R)                      \
                              + (size_t)(nb * 64 + lrow_) * K_R + (k0) + q_ * 8;      \
            asm volatile("cp.async.cg.shared.global [%0], [%1], 16;"                  \
                :: "r"(sb_ + (uint32_t)(A_REG_B + str_ * B_ST_B + lrow_ * ROW_B + q_ * 16)), \
                   "l"(gm_));                                                         \
        }                                                                             \
    } while (0)

    float acc[4][4][4];
#pragma unroll
    for (int mi = 0; mi < 4; mi++)
#pragma unroll
        for (int ni = 0; ni < 4; ni++)
#pragma unroll
            for (int q = 0; q < 4; q++) acc[mi][ni][q] = 0.0f;

    LOADG(0, 0);
    asm volatile("cp.async.commit_group;" ::: "memory");
    LOADG(1, 64);
    asm volatile("cp.async.commit_group;" ::: "memory");

    // fragment offsets (halfs, within a stage)
    const int aOff = p * (A_ST_B / 2) + (wm * 64 + lr) * BKP_H + 16 * lc;
    const int bOff = (A_REG_B / 2) + p * (B_ST_B / 2) + (wn * 32 + lr) * BKP_H + 16 * lc;

    for (int it = 0; it < NITER; ++it) {
        const int buf = it & 1;
        asm volatile("cp.async.wait_group 1;" ::: "memory");
        __syncthreads();

        const __half* As = smem + (size_t)buf * (STAGE_B / 2);
        COMPUTE_STAGE(As + aOff, As + bOff);

        __syncthreads();
        if (it + 2 < NITER) LOADG(buf, (it + 2) * 64);
        asm volatile("cp.async.commit_group;" ::: "memory");
    }

    asm volatile("cp.async.wait_group 0;" ::: "memory");
    __syncthreads();

    // ---- epilogue: products -> smem fp32, Gauss combine, blades, store ----
    float* epf = reinterpret_cast<float*>(smem);
    {
        float* base = epf + p * EPPROD + (wm * 64) * EPROW + wn * 32;
#pragma unroll
        for (int mi = 0; mi < 4; mi++)
#pragma unroll
            for (int ni = 0; ni < 4; ni++) {
                *reinterpret_cast<float2*>(base + (mi * 16 + lr    ) * EPROW + ni * 8 + 2 * lc) =
                    make_float2(acc[mi][ni][0], acc[mi][ni][1]);
                *reinterpret_cast<float2*>(base + (mi * 16 + lr + 8) * EPROW + ni * 8 + 2 * lc) =
                    make_float2(acc[mi][ni][2], acc[mi][ni][3]);
            }
    }
    __syncthreads();

    const float* M1 = epf;
    const float* M2 = epf + EPPROD;
    const float* M3 = epf + 2 * EPPROD;
    for (int t = tid; t < 2048; t += 384) {
        int b_l = t >> 5, o_l = t & 31;
        int rA = (2 * b_l) * EPROW + 2 * o_l;     // row c=0, col r=0
        int rB = rA + EPROW;                      // row c=1
        float m1a0 = M1[rA], m1a1 = M1[rA + 1], m2a0 = M2[rA], m2a1 = M2[rA + 1];
        float m3a0 = M3[rA], m3a1 = M3[rA + 1];
        float m1b0 = M1[rB], m1b1 = M1[rB + 1], m2b0 = M2[rB], m2b1 = M2[rB + 1];
        float m3b0 = M3[rB], m3b1 = M3[rB + 1];
        float A0 = m1a0 - m2a0;                   // Re Y(0,0)
        float A1 = m1a1 - m2a1;                   // Re Y(1,0)
        float A2 = m3a0 - m1a0 - m2a0;            // Im Y(0,0)
        float A3 = m3a1 - m1a1 - m2a1;            // Im Y(1,0)
        float B0 = m1b0 - m2b0;                   // Re Y(0,1)
        float B1 = m1b1 - m2b1;                   // Re Y(1,1)
        float B2 = m3b0 - m1b0 - m2b0;            // Im Y(0,1)
        float B3 = m3b1 - m1b1 - m2b1;            // Im Y(1,1)
        int o = nb * 32 + o_l;
        float* Crow = C + (size_t)((block_m >> 1) + b_l) * (COUT * 8);
        float4 bv0 = *reinterpret_cast<const float4*>(bias + o * 8);
        float4 bv1 = *reinterpret_cast<const float4*>(bias + o * 8 + 4);
        float4 u, v;
        u.x = A0 + B1 + bv0.x;  u.y = B0 + A1 + bv0.y;
        u.z = A3 - B2 + bv0.z;  u.w = A2 - B3 + bv0.w;
        v.x = A0 - B1 + bv1.x;  v.y = A1 - B0 + bv1.y;
        v.z = B2 + A3 + bv1.z;  v.w = A2 + B3 + bv1.w;
        *reinterpret_cast<float4*>(Crow + o * 8    ) = u;
        *reinterpret_cast<float4*>(Crow + o * 8 + 4) = v;
    }
}

// ---------------------------------------------------------------------------
// Launch.  Inputs: x, weight, bias, cayley (metadata order).
// ---------------------------------------------------------------------------
extern "C" void kernel_launch(void* const* d_in, const int* in_sizes, int n_in,
                              void* d_out, int out_size) {
    const float* x      = (const float*)d_in[0];   // [8192, 256, 8]
    const float* weight = (const float*)d_in[1];   // [256, 256, 8]
    const float* bias   = (const float*)d_in[2];   // [256, 8]
    float* out = (float*)d_out;                    // [8192, 256, 8]
    (void)in_sizes; (void)n_in; (void)out_size;

    a_transform_kernel<<<(B_DIM * CIN) / 1024, 1024>>>((const float4*)x);
    b_transform_kernel<<<(COUT * CIN) / 1024, 1024>>>(weight);

    cudaFuncSetAttribute(gemm_gauss_kernel,
                         cudaFuncAttributeMaxDynamicSharedMemorySize, SMEM_TOTAL);
    dim3 grid(N_C / 64, M_A / 128);   // (8, 128) = 1024 CTAs
    gemm_gauss_kernel<<<grid, 384, SMEM_TOTAL>>>(bias, out);
}

// round 16
// speedup vs baseline: 1.0442x; 1.0442x over previous
#include <cuda_runtime.h>
#include <cuda_fp16.h>
#include <cstdint>

// ---------------------------------------------------------------------------
// CliffordLinear via Cl(3,0) ~= M2(C) + GAUSS 3-multiplication complex GEMM.
//   M1 = Ar.Br^T, M2 = Ai.Bi^T, M3 = (Ar+Ai).(Br+Bi)^T
//   Re Y = M1 - M2,  Im Y = M3 - M1 - M2      (12.9 G-MAC, fp16 x fp16 + fp32)
// This round: 192-thread CTAs, 64x64 complex tiles, 2 CTAs/SM (R15 ran 1/SM
// and exposed every barrier; cross-CTA overlap is what made R12 efficient).
// ---------------------------------------------------------------------------

#define B_DIM 8192
#define CIN  256
#define COUT 256
#define M_A  16384          /* A real rows (b,c) */
#define K_R  512            /* real k per product */
#define N_C  512            /* real cols (o,r) of the complex-part products */

__device__ __half g_A[3 * M_A * K_R];     // 48 MB  (Ar | Ai | As)
__device__ __half g_B[3 * N_C * K_R];     // 1.5 MB (Br | Bi | Bs)

// ---------------------------------------------------------------------------
// Prologue 1: x -> Ar, Ai, As.  One thread per (b,i).
// ---------------------------------------------------------------------------
__global__ void __launch_bounds__(1024) a_transform_kernel(const float4* __restrict__ x4) {
    int t = blockIdx.x * 1024 + threadIdx.x;       // (b,i)
    float4 v0 = x4[2 * t];                          // x0..x3
    float4 v1 = x4[2 * t + 1];                      // x4..x7
    int b = t >> 8, i = t & 255;
    __half2* Ar = reinterpret_cast<__half2*>(g_A);
    __half2* Ai = Ar + (M_A * K_R / 2);
    __half2* As = Ai + (M_A * K_R / 2);
    int r0 = (2 * b) * 256 + i;                    // row 2b (c=0), col pair i
    int r1 = r0 + 256;                             // row 2b+1 (c=1)
    float re0a = v0.x + v1.x, re0b = v0.y + v1.y;  // Re m00, Re m10
    float im0a = v0.w + v1.w, im0b = v0.z + v1.z;  // Im m00, Im m10
    float re1a = v0.y - v1.y, re1b = v0.x - v1.x;  // Re m01, Re m11
    float im1a = v1.z - v0.z, im1b = v1.w - v0.w;  // Im m01, Im m11
    Ar[r0] = __floats2half2_rn(re0a, re0b);
    Ai[r0] = __floats2half2_rn(im0a, im0b);
    As[r0] = __floats2half2_rn(re0a + im0a, re0b + im0b);
    Ar[r1] = __floats2half2_rn(re1a, re1b);
    Ai[r1] = __floats2half2_rn(im1a, im1b);
    As[r1] = __floats2half2_rn(re1a + im1a, re1b + im1b);
}

// ---------------------------------------------------------------------------
// Prologue 2: weight -> Br, Bi, Bs (x 0.5).  One thread per (o,i).
// ---------------------------------------------------------------------------
__global__ void __launch_bounds__(1024) b_transform_kernel(const float* __restrict__ w) {
    int t = blockIdx.x * 1024 + threadIdx.x;       // (o,i)
    int o = t >> 8, i = t & 255;
    const float* p = w + (size_t)t * 8;
    float w0 = p[0], w1 = p[1], w2 = p[2], w3 = p[3];
    float w4 = p[4], w5 = p[5], w6 = p[6], w7 = p[7];
    float Rm00 = .5f * (w0 + w4), Rm01 = .5f * (w1 - w5);
    float Rm10 = .5f * (w1 + w5), Rm11 = .5f * (w0 - w4);
    float Im00 = .5f * (w3 + w7), Im01 = .5f * (w6 - w2);
    float Im10 = .5f * (w2 + w6), Im11 = .5f * (w7 - w3);
    __half2* Br = reinterpret_cast<__half2*>(g_B);
    __half2* Bi = Br + (N_C * K_R / 2);
    __half2* Bs = Bi + (N_C * K_R / 2);
    int r0 = (2 * o) * 256 + i;                    // row 2o (r=0)
    int r1 = r0 + 256;                             // row 2o+1 (r=1)
    Br[r0] = __floats2half2_rn(Rm00, Rm01);
    Bi[r0] = __floats2half2_rn(Im00, Im01);
    Bs[r0] = __floats2half2_rn(Rm00 + Im00, Rm01 + Im01);
    Br[r1] = __floats2half2_rn(Rm10, Rm11);
    Bi[r1] = __floats2half2_rn(Im10, Im11);
    Bs[r1] = __floats2half2_rn(Rm10 + Im10, Rm11 + Im11);
}

// ---------------------------------------------------------------------------
// GEMM: CTA = 192 threads (6 warps), 2 CTAs/SM.  Tile: 64 A-rows x 64 cols,
// 3 products; warp w: product w>>1, 64x32 sub-tile (wn = w&1).
// k-stage 64, 2-buffer cp.async pipeline, 8 iterations.
// smem stage: [Ar|Ai|As](3 x 64 x 144B) + [Br|Bi|Bs](3 x 64 x 144B) = 55296 B.
// ---------------------------------------------------------------------------
#define BKP_H 72
#define ROW_B 144
#define A_ST_B (64 * ROW_B)                /* 9216 per stream */
#define B_ST_B (64 * ROW_B)                /* 9216 per stream */
#define A_REG_B (3 * A_ST_B)               /* 27648 */
#define STAGE_B (A_REG_B + 3 * B_ST_B)     /* 55296 */
#define SMEM_TOTAL (2 * STAGE_B)           /* 110592 -> 2 CTAs/SM */
#define NITER 8                            /* 512 / 64 */

__device__ __forceinline__ void mma_f16(float& c0, float& c1, float& c2, float& c3,
                                        uint32_t a0, uint32_t a1, uint32_t a2, uint32_t a3,
                                        uint32_t b0, uint32_t b1) {
    asm volatile(
        "mma.sync.aligned.m16n8k16.row.col.f32.f16.f16.f32 "
        "{%0,%1,%2,%3}, {%4,%5,%6,%7}, {%8,%9}, {%0,%1,%2,%3};"
        : "+f"(c0), "+f"(c1), "+f"(c2), "+f"(c3)
        : "r"(a0), "r"(a1), "r"(a2), "r"(a3), "r"(b0), "r"(b1));
}

#define COMPUTE_STAGE(aP, bP)                                                         \
    _Pragma("unroll")                                                                 \
    for (int q = 0; q < 2; q++) {                                                     \
        uint4 fb[4];                                                                  \
        _Pragma("unroll")                                                             \
        for (int ni = 0; ni < 4; ni++)                                                \
            fb[ni] = *reinterpret_cast<const uint4*>((bP) + ni * 8 * BKP_H + 8 * q);  \
        _Pragma("unroll")                                                             \
        for (int mi = 0; mi < 4; mi++) {                                              \
            uint4 fa0 = *reinterpret_cast<const uint4*>((aP) + (mi * 16    ) * BKP_H + 8 * q); \
            uint4 fa1 = *reinterpret_cast<const uint4*>((aP) + (mi * 16 + 8) * BKP_H + 8 * q); \
            const uint32_t* pa0 = &fa0.x;                                             \
            const uint32_t* pa1 = &fa1.x;                                             \
            _Pragma("unroll")                                                         \
            for (int kk = 0; kk < 2; kk++) {                                          \
                uint32_t a0 = pa0[2 * kk], a2 = pa0[2 * kk + 1];                      \
                uint32_t a1 = pa1[2 * kk], a3 = pa1[2 * kk + 1];                      \
                _Pragma("unroll")                                                     \
                for (int ni = 0; ni < 4; ni++) {                                      \
                    const uint32_t* pb = &fb[ni].x;                                   \
                    mma_f16(acc[mi][ni][0], acc[mi][ni][1],                           \
                            acc[mi][ni][2], acc[mi][ni][3],                           \
                            a0, a1, a2, a3, pb[2 * kk], pb[2 * kk + 1]);              \
                }                                                                     \
            }                                                                         \
        }                                                                             \
    }

#define EPROW 66                            /* epilogue row stride, floats */
#define EPPROD (64 * EPROW)                 /* 4224 floats per product */

__global__ void __launch_bounds__(192, 2) gemm_gauss_kernel(
    const float* __restrict__ bias, float* __restrict__ C)
{
    extern __shared__ __half smem[];
    const int tid  = threadIdx.x;
    const int wid  = tid >> 5;              // 0..5
    const int lane = tid & 31;
    const int p  = wid >> 1;                // product 0..2
    const int wn = wid & 1;                 // N sub-tile
    const int lr = lane >> 2, lc = lane & 3;
    const int block_m = blockIdx.y * 64;    // A-row base
    const int nb = blockIdx.x;              // col tile (64 each)

    uint32_t smem_u;
    asm("{ .reg .u64 t; cvta.to.shared.u64 t, %1; cvt.u32.u64 %0, t; }"
        : "=r"(smem_u) : "l"(smem));

    // Loader: A 1536 16B-chunks (8/thread), B 1536 (8/thread)
#define LOADG(buf, k0) do {                                                           \
        uint32_t sb_ = smem_u + (uint32_t)(buf) * STAGE_B;                            \
        _Pragma("unroll")                                                             \
        for (int j_ = 0; j_ < 8; j_++) {                                              \
            int idx_ = j_ * 192 + tid;                                                \
            int row_ = idx_ >> 3, q_ = idx_ & 7;                                      \
            int str_ = row_ >> 6, lrow_ = row_ & 63;                                  \
            const __half* gm_ = g_A + (size_t)str_ * (M_A * K_R)                      \
                              + (size_t)(block_m + lrow_) * K_R + (k0) + q_ * 8;      \
            asm volatile("cp.async.cg.shared.global [%0], [%1], 16;"                  \
                :: "r"(sb_ + (uint32_t)(str_ * A_ST_B + lrow_ * ROW_B + q_ * 16)),    \
                   "l"(gm_));                                                         \
        }                                                                             \
        _Pragma("unroll")                                                             \
        for (int j_ = 0; j_ < 8; j_++) {                                              \
            int idx_ = j_ * 192 + tid;                                                \
            int row_ = idx_ >> 3, q_ = idx_ & 7;                                      \
            int str_ = row_ >> 6, lrow_ = row_ & 63;                                  \
            const __half* gm_ = g_B + (size_t)str_ * (N_C * K_R)                      \
                              + (size_t)(nb * 64 + lrow_) * K_R + (k0) + q_ * 8;      \
            asm volatile("cp.async.cg.shared.global [%0], [%1], 16;"                  \
                :: "r"(sb_ + (uint32_t)(A_REG_B + str_ * B_ST_B + lrow_ * ROW_B + q_ * 16)), \
                   "l"(gm_));                                                         \
        }                                                                             \
    } while (0)

    float acc[4][4][4];
#pragma unroll
    for (int mi = 0; mi < 4; mi++)
#pragma unroll
        for (int ni = 0; ni < 4; ni++)
#pragma unroll
            for (int q = 0; q < 4; q++) acc[mi][ni][q] = 0.0f;

    LOADG(0, 0);
    asm volatile("cp.async.commit_group;" ::: "memory");
    LOADG(1, 64);
    asm volatile("cp.async.commit_group;" ::: "memory");

    // fragment offsets (halfs, within a stage); warp tile = full 64 rows x 32 cols
    const int aOff = p * (A_ST_B / 2) + lr * BKP_H + 16 * lc;
    const int bOff = (A_REG_B / 2) + p * (B_ST_B / 2) + (wn * 32 + lr) * BKP_H + 16 * lc;

    for (int it = 0; it < NITER; ++it) {
        const int buf = it & 1;
        asm volatile("cp.async.wait_group 1;" ::: "memory");
        __syncthreads();

        const __half* As = smem + (size_t)buf * (STAGE_B / 2);
        COMPUTE_STAGE(As + aOff, As + bOff);

        __syncthreads();
        if (it + 2 < NITER) LOADG(buf, (it + 2) * 64);
        asm volatile("cp.async.commit_group;" ::: "memory");
    }

    asm volatile("cp.async.wait_group 0;" ::: "memory");
    __syncthreads();

    // ---- epilogue: products -> smem fp32, Gauss combine, blades, store ----
    float* epf = reinterpret_cast<float*>(smem);
    {
        float* base = epf + p * EPPROD + wn * 32;
#pragma unroll
        for (int mi = 0; mi < 4; mi++)
#pragma unroll
            for (int ni = 0; ni < 4; ni++) {
                *reinterpret_cast<float2*>(base + (mi * 16 + lr    ) * EPROW + ni * 8 + 2 * lc) =
                    make_float2(acc[mi][ni][0], acc[mi][ni][1]);
                *reinterpret_cast<float2*>(base + (mi * 16 + lr + 8) * EPROW + ni * 8 + 2 * lc) =
                    make_float2(acc[mi][ni][2], acc[mi][ni][3]);
            }
    }
    __syncthreads();

    const float* M1 = epf;
    const float* M2 = epf + EPPROD;
    const float* M3 = epf + 2 * EPPROD;
    // 32 b x 32 o outputs per CTA
    for (int t = tid; t < 1024; t += 192) {
        int b_l = t >> 5, o_l = t & 31;
        int rA = (2 * b_l) * EPROW + 2 * o_l;     // row c=0, cols (r=0, r=1)
        int rB = rA + EPROW;                      // row c=1
        float m1a0 = M1[rA], m1a1 = M1[rA + 1], m2a0 = M2[rA], m2a1 = M2[rA + 1];
        float m3a0 = M3[rA], m3a1 = M3[rA + 1];
        float m1b0 = M1[rB], m1b1 = M1[rB + 1], m2b0 = M2[rB], m2b1 = M2[rB + 1];
        float m3b0 = M3[rB], m3b1 = M3[rB + 1];
        float A0 = m1a0 - m2a0;                   // Re Y(0,0)
        float A1 = m1a1 - m2a1;                   // Re Y(1,0)
        float A2 = m3a0 - m1a0 - m2a0;            // Im Y(0,0)
        float A3 = m3a1 - m1a1 - m2a1;            // Im Y(1,0)
        float B0 = m1b0 - m2b0;                   // Re Y(0,1)
        float B1 = m1b1 - m2b1;                   // Re Y(1,1)
        float B2 = m3b0 - m1b0 - m2b0;            // Im Y(0,1)
        float B3 = m3b1 - m1b1 - m2b1;            // Im Y(1,1)
        int o = nb * 32 + o_l;
        float* Crow = C + (size_t)((block_m >> 1) + b_l) * (COUT * 8);
        float4 bv0 = *reinterpret_cast<const float4*>(bias + o * 8);
        float4 bv1 = *reinterpret_cast<const float4*>(bias + o * 8 + 4);
        float4 u, v;
        u.x = A0 + B1 + bv0.x;  u.y = B0 + A1 + bv0.y;
        u.z = A3 - B2 + bv0.z;  u.w = A2 - B3 + bv0.w;
        v.x = A0 - B1 + bv1.x;  v.y = A1 - B0 + bv1.y;
        v.z = B2 + A3 + bv1.z;  v.w = A2 + B3 + bv1.w;
        *reinterpret_cast<float4*>(Crow + o * 8    ) = u;
        *reinterpret_cast<float4*>(Crow + o * 8 + 4) = v;
    }
}

// ---------------------------------------------------------------------------
// Launch.  Inputs: x, weight, bias, cayley (metadata order).
// ---------------------------------------------------------------------------
extern "C" void kernel_launch(void* const* d_in, const int* in_sizes, int n_in,
                              void* d_out, int out_size) {
    const float* x      = (const float*)d_in[0];   // [8192, 256, 8]
    const float* weight = (const float*)d_in[1];   // [256, 256, 8]
    const float* bias   = (const float*)d_in[2];   // [256, 8]
    float* out = (float*)d_out;                    // [8192, 256, 8]
    (void)in_sizes; (void)n_in; (void)out_size;

    a_transform_kernel<<<(B_DIM * CIN) / 1024, 1024>>>((const float4*)x);
    b_transform_kernel<<<(COUT * CIN) / 1024, 1024>>>(weight);

    cudaFuncSetAttribute(gemm_gauss_kernel,
                         cudaFuncAttributeMaxDynamicSharedMemorySize, SMEM_TOTAL);
    dim3 grid(N_C / 64, M_A / 64);   // (8, 256) = 2048 CTAs
    gemm_gauss_kernel<<<grid, 192, SMEM_TOTAL>>>(bias, out);
}